// round 9
// baseline (speedup 1.0000x reference)
#include <cuda_runtime.h>
#include <cuda_fp16.h>
#include <cstdint>

#define B_    64
#define J_    1024
#define M_    256
#define NC_   32
#define DC_   32
#define EPS_  1e-7f
#define SEG_  8

// Scratch
__device__ float  g_xsump[SEG_ * B_ * M_];
__device__ float  g_cxp  [SEG_ * B_ * NC_ * M_];
__device__ __half g_wvh  [B_ * NC_ * M_];
__device__ __half g_wvl  [B_ * NC_ * M_];
__device__ __half g_ch   [B_ * NC_ * J_];    // c hi plane, [b][i][j]
__device__ __half g_cl   [B_ * NC_ * J_];    // c lo plane (x4096)
__device__ __half g_xh   [B_ * J_ * M_];     // x hi plane, row layout [b][j][m]
__device__ __half g_xl   [B_ * J_ * M_];
__device__ __half g_xhT  [B_ * M_ * J_];     // x hi plane, transposed [b][m][j]
__device__ __half g_xlT  [B_ * M_ * J_];

// ---------- helpers ----------
__device__ __forceinline__ void splitf(float f, __half& h, __half& l) {
    h = __float2half_rn(f);
    l = __float2half_rn((f - __half2float(h)) * 4096.0f);
}

__device__ __forceinline__ void mma16816(float& c0, float& c1, float& c2, float& c3,
                                         uint32_t a0, uint32_t a1, uint32_t a2, uint32_t a3,
                                         uint32_t b0, uint32_t b1) {
    asm volatile(
        "mma.sync.aligned.m16n8k16.row.col.f32.f16.f16.f32 "
        "{%0,%1,%2,%3}, {%4,%5,%6,%7}, {%8,%9}, {%0,%1,%2,%3};"
        : "+f"(c0), "+f"(c1), "+f"(c2), "+f"(c3)
        : "r"(a0), "r"(a1), "r"(a2), "r"(a3), "r"(b0), "r"(b1));
}

// ---------- prep: x -> hi/lo row planes + xsum partials ----------
__global__ void __launch_bounds__(256) k_prep(const float* __restrict__ x) {
    __shared__ float4 sred[4][64];
    int b = blockIdx.x, seg = blockIdx.y;
    int t = threadIdx.x;
    int jj = t >> 6, mq = t & 63;
    float4 s = {0.f, 0.f, 0.f, 0.f};
    for (int it = 0; it < 32; ++it) {
        int j = seg * 128 + jj + 4 * it;
        size_t off = ((size_t)b * J_ + j) * M_ + mq * 4;
        float4 v = *(const float4*)(x + off);
        __half h0, l0, h1, l1, h2, l2, h3, l3;
        splitf(v.x, h0, l0); splitf(v.y, h1, l1);
        splitf(v.z, h2, l2); splitf(v.w, h3, l3);
        uint2 uh, ul;
        ((__half2*)&uh)[0] = __halves2half2(h0, h1);
        ((__half2*)&uh)[1] = __halves2half2(h2, h3);
        ((__half2*)&ul)[0] = __halves2half2(l0, l1);
        ((__half2*)&ul)[1] = __halves2half2(l2, l3);
        *(uint2*)(g_xh + off) = uh;
        *(uint2*)(g_xl + off) = ul;
        s.x += v.x; s.y += v.y; s.z += v.z; s.w += v.w;
    }
    sred[jj][mq] = s;
    __syncthreads();
    if (t < 64) {
        float4 a = sred[0][t], c1 = sred[1][t], c2 = sred[2][t], c3 = sred[3][t];
        a.x += c1.x + c2.x + c3.x; a.y += c1.y + c2.y + c3.y;
        a.z += c1.z + c2.z + c3.z; a.w += c1.w + c2.w + c3.w;
        *(float4*)(g_xsump + ((size_t)seg * B_ + b) * M_ + t * 4) = a;
    }
}

// ---------- prepT: x -> hi/lo transposed planes [b][m][j] ----------
__global__ void __launch_bounds__(256) k_prepT(const float* __restrict__ x) {
    __shared__ __half Th[64 * 136];
    __shared__ __half Tl[64 * 136];
    int b = blockIdx.x, cc = blockIdx.y;        // cc 0..31
    int j0 = (cc >> 2) * 128, mc = (cc & 3) * 64;
    int t = threadIdx.x;
#pragma unroll
    for (int c = 0; c < 8; ++c) {
        int lin = t + 256 * c;                  // 2048 float4 = 128 j x 16 mq
        int j = lin >> 4, mq = lin & 15;
        float4 v = *(const float4*)(x + ((size_t)b * J_ + j0 + j) * M_ + mc + mq * 4);
        __half h, l;
        splitf(v.x, h, l); Th[(mq * 4 + 0) * 136 + j] = h; Tl[(mq * 4 + 0) * 136 + j] = l;
        splitf(v.y, h, l); Th[(mq * 4 + 1) * 136 + j] = h; Tl[(mq * 4 + 1) * 136 + j] = l;
        splitf(v.z, h, l); Th[(mq * 4 + 2) * 136 + j] = h; Tl[(mq * 4 + 2) * 136 + j] = l;
        splitf(v.w, h, l); Th[(mq * 4 + 3) * 136 + j] = h; Tl[(mq * 4 + 3) * 136 + j] = l;
    }
    __syncthreads();
#pragma unroll
    for (int c = 0; c < 4; ++c) {
        int idx = t + 256 * c;                  // 1024 uint4 per plane
        int m = idx >> 4, jq = idx & 15;
        uint4 vh = *(const uint4*)(Th + m * 136 + jq * 8);
        uint4 vl = *(const uint4*)(Tl + m * 136 + jq * 8);
        size_t off = ((size_t)b * M_ + mc + m) * J_ + j0 + jq * 8;
        *(uint4*)(g_xhT + off) = vh;
        *(uint4*)(g_xlT + off) = vl;
    }
}

// ---------- caps: out = squash(row @ W_i); Wv = W_i @ out (as hi/lo halves) ----------
template <int MODE>
__global__ void __launch_bounds__(256) k_caps(const float* __restrict__ W, float* __restrict__ out) {
    __shared__ float Wsh[M_ * 33];
    __shared__ float rowsh[M_];
    __shared__ float psh[8 * 32];
    __shared__ float osh[NC_];
    int t = threadIdx.x;
    int i = blockIdx.x, bg = blockIdx.y;

#pragma unroll
    for (int c = 0; c < 32; ++c) {
        int lin = t + 256 * c;
        int m = lin >> 5, k = lin & 31;
        Wsh[m * 33 + k] = W[m * (NC_ * DC_) + i * DC_ + k];
    }

    for (int bb = 0; bb < 8; ++bb) {
        int b = bg * 8 + bb;
        float r = 0.f;
        if (MODE == 0) {
#pragma unroll
            for (int s = 0; s < SEG_; ++s) r += g_xsump[((size_t)s * B_ + b) * M_ + t];
        } else {
#pragma unroll
            for (int s = 0; s < SEG_; ++s)
                r += g_cxp[(((size_t)s * B_ + b) * NC_ + i) * M_ + t];
        }
        __syncthreads();
        rowsh[t] = r;
        __syncthreads();

        {
            int k = t & 31, g = t >> 5;
            float p = 0.f;
#pragma unroll
            for (int mm = 0; mm < 32; ++mm)
                p += rowsh[g * 32 + mm] * Wsh[(g * 32 + mm) * 33 + k];
            psh[g * 32 + k] = p;
        }
        __syncthreads();

        if (t < 32) {
            float s = 0.f;
#pragma unroll
            for (int g = 0; g < 8; ++g) s += psh[g * 32 + t];
            float v = (MODE == 0) ? s * (1.0f / 32.0f) : s;
            float sq = v * v;
#pragma unroll
            for (int off = 16; off; off >>= 1) sq += __shfl_xor_sync(0xffffffffu, sq, off);
            float o = v / sqrtf(sq + EPS_);
            osh[t] = o;
            if (MODE == 2) out[((size_t)b * NC_ + i) * DC_ + t] = o;
        }
        __syncthreads();

        if (MODE != 2) {
            float wv = 0.f;
#pragma unroll
            for (int k = 0; k < 32; ++k) wv += Wsh[t * 33 + k] * osh[k];
            __half h, l;
            splitf(wv, h, l);
            g_wvh[((size_t)b * NC_ + i) * M_ + t] = h;
            g_wvl[((size_t)b * NC_ + i) * M_ + t] = l;
        }
        __syncthreads();
    }
}

// ---------- logits + softmax (tensor core, vectorized staging) ----------
// grid (64, 8), block 256 = 8 warps. Block tile 128 j x 32 i, K = 256 m.
// smem (halves): WH[32][264] @0, WL @8448, XH[128][72] @16896, XL @26112.
__global__ void __launch_bounds__(256, 2) k_logits(const float* __restrict__ x) {
    extern __shared__ __half sm[];
    __half* WH = sm;
    __half* WL = sm + 8448;
    __half* XH = sm + 16896;
    __half* XL = sm + 26112;
    float*  b1 = (float*)(sm + 16896);   // [128][33], reuses XH/XL after mainloop

    int t = threadIdx.x, lane = t & 31, w = t >> 5;
    int g = lane >> 2, tig = lane & 3;
    int b = blockIdx.x, j0 = blockIdx.y * 128;

    // stage Wv planes (vector copies)
#pragma unroll
    for (int c = 0; c < 4; ++c) {
        int lin = t + 256 * c;           // 1024 uint4 per plane
        int i = lin >> 5, mq = lin & 31;
        size_t so = ((size_t)b * NC_ + i) * M_ + mq * 8;
        *(uint4*)(WH + i * 264 + mq * 8) = *(const uint4*)(g_wvh + so);
        *(uint4*)(WL + i * 264 + mq * 8) = *(const uint4*)(g_wvl + so);
    }

    float hh[4][4], lo[4][4];
#pragma unroll
    for (int nt = 0; nt < 4; ++nt)
#pragma unroll
        for (int q = 0; q < 4; ++q) { hh[nt][q] = 0.f; lo[nt][q] = 0.f; }

    for (int kc = 0; kc < 4; ++kc) {     // m-chunks of 64
        __syncthreads();
#pragma unroll
        for (int c = 0; c < 4; ++c) {
            int lin = t + 256 * c;       // 1024 uint4 per plane
            int j = lin >> 3, mq = lin & 7;
            size_t so = ((size_t)b * J_ + j0 + j) * M_ + kc * 64 + mq * 8;
            *(uint4*)(XH + j * 72 + mq * 8) = *(const uint4*)(g_xh + so);
            *(uint4*)(XL + j * 72 + mq * 8) = *(const uint4*)(g_xl + so);
        }
        __syncthreads();

        const uint32_t* XH2 = (const uint32_t*)XH;
        const uint32_t* XL2 = (const uint32_t*)XL;
        const uint32_t* WH2 = (const uint32_t*)WH;
        const uint32_t* WL2 = (const uint32_t*)WL;
#pragma unroll
        for (int ks = 0; ks < 4; ++ks) { // k16 steps within chunk
            int ab = (w * 16 + g) * 36 + ks * 8 + tig;
            uint32_t ah0 = XH2[ab],           ah1 = XH2[ab + 288];
            uint32_t ah2 = XH2[ab + 4],       ah3 = XH2[ab + 292];
            uint32_t al0 = XL2[ab],           al1 = XL2[ab + 288];
            uint32_t al2 = XL2[ab + 4],       al3 = XL2[ab + 292];
            int km = kc * 32 + ks * 8;
#pragma unroll
            for (int nt = 0; nt < 4; ++nt) {
                int bb = (nt * 8 + g) * 132 + km + tig;
                uint32_t bh0 = WH2[bb], bh1 = WH2[bb + 4];
                uint32_t bl0 = WL2[bb], bl1 = WL2[bb + 4];
                mma16816(hh[nt][0], hh[nt][1], hh[nt][2], hh[nt][3],
                         ah0, ah1, ah2, ah3, bh0, bh1);
                mma16816(lo[nt][0], lo[nt][1], lo[nt][2], lo[nt][3],
                         al0, al1, al2, al3, bh0, bh1);
                mma16816(lo[nt][0], lo[nt][1], lo[nt][2], lo[nt][3],
                         ah0, ah1, ah2, ah3, bl0, bl1);
            }
        }
    }
    __syncthreads();

    // combine + write logits to b1[j][i]
#pragma unroll
    for (int nt = 0; nt < 4; ++nt) {
        int col = nt * 8 + 2 * tig;
        int row = w * 16 + g;
        b1[row * 33 + col]           = hh[nt][0] + lo[nt][0] * (1.0f / 4096.0f);
        b1[row * 33 + col + 1]       = hh[nt][1] + lo[nt][1] * (1.0f / 4096.0f);
        b1[(row + 8) * 33 + col]     = hh[nt][2] + lo[nt][2] * (1.0f / 4096.0f);
        b1[(row + 8) * 33 + col + 1] = hh[nt][3] + lo[nt][3] * (1.0f / 4096.0f);
    }
    __syncthreads();

    // softmax over i per j; stage c hi/lo into smem (reuse WH/WL), then vector STG
    if (t < 128) {
        float* row = b1 + t * 33;
        float mx = row[0];
#pragma unroll
        for (int i = 1; i < 32; ++i) mx = fmaxf(mx, row[i]);
        float s = 0.f;
        float e[32];
#pragma unroll
        for (int i = 0; i < 32; ++i) { e[i] = __expf(row[i] - mx); s += e[i]; }
        float inv = 1.0f / s;
#pragma unroll
        for (int i = 0; i < 32; ++i) {
            __half h, l;
            splitf(e[i] * inv, h, l);
            WH[i * 136 + t] = h;         // c-hi staged [i][j]
            WL[i * 136 + t] = l;
        }
    }
    __syncthreads();
#pragma unroll
    for (int c = 0; c < 2; ++c) {
        int lin = t + 256 * c;           // 512 uint4 per plane
        int i = lin >> 4, jq = lin & 15;
        size_t off = ((size_t)b * NC_ + i) * J_ + j0 + jq * 8;
        *(uint4*)(g_ch + off) = *(const uint4*)(WH + i * 136 + jq * 8);
        *(uint4*)(g_cl + off) = *(const uint4*)(WL + i * 136 + jq * 8);
    }
}

// ---------- cx partials (tensor core, vectorized staging) ----------
// grid (64 b, 8 seg), block 256 = 8 warps. K = 128 j in 4 chunks of 32.
__global__ void __launch_bounds__(256) k_cx(const float* __restrict__ x) {
    __shared__ __half XT[2][256 * 40];   // [plane][m][j-pad40]
    __shared__ __half CT[2][32 * 40];    // [plane][i][j-pad40]

    int t = threadIdx.x, lane = t & 31, w = t >> 5;
    int g = lane >> 2, tig = lane & 3;
    int b = blockIdx.x, seg = blockIdx.y;

    float hh[2][4][4], lo[2][4][4];
#pragma unroll
    for (int it = 0; it < 2; ++it)
#pragma unroll
        for (int nt = 0; nt < 4; ++nt)
#pragma unroll
            for (int q = 0; q < 4; ++q) { hh[it][nt][q] = 0.f; lo[it][nt][q] = 0.f; }

    for (int jc = 0; jc < 4; ++jc) {     // j-chunks of 32
        __syncthreads();
        int jb = seg * 128 + jc * 32;
        // stage xT planes: vector copies from g_xhT/g_xlT
#pragma unroll
        for (int c = 0; c < 4; ++c) {
            int lin = t + 256 * c;       // 1024 uint4 per plane
            int m = lin >> 2, jq = lin & 3;
            size_t so = ((size_t)b * M_ + m) * J_ + jb + jq * 8;
            *(uint4*)(XT[0] + m * 40 + jq * 8) = *(const uint4*)(g_xhT + so);
            *(uint4*)(XT[1] + m * 40 + jq * 8) = *(const uint4*)(g_xlT + so);
        }
        // stage c planes
        if (t < 128) {
            int i = t >> 2, jq = t & 3;  // 128 uint4 per plane
            size_t so = ((size_t)b * NC_ + i) * J_ + jb + jq * 8;
            *(uint4*)(CT[0] + i * 40 + jq * 8) = *(const uint4*)(g_ch + so);
            *(uint4*)(CT[1] + i * 40 + jq * 8) = *(const uint4*)(g_cl + so);
        }
        __syncthreads();

        const uint32_t* XTH = (const uint32_t*)XT[0];
        const uint32_t* XTL = (const uint32_t*)XT[1];
        const uint32_t* CTH = (const uint32_t*)CT[0];
        const uint32_t* CTL = (const uint32_t*)CT[1];
#pragma unroll
        for (int ks = 0; ks < 2; ++ks) { // 2 k16-steps per chunk
            int k0w = ks * 8;
            uint32_t ah[2][4], al[2][4];
#pragma unroll
            for (int it = 0; it < 2; ++it) {
                int ab = (it * 16 + g) * 20 + k0w + tig;
                ah[it][0] = CTH[ab];       ah[it][1] = CTH[ab + 160];
                ah[it][2] = CTH[ab + 4];   ah[it][3] = CTH[ab + 164];
                al[it][0] = CTL[ab];       al[it][1] = CTL[ab + 160];
                al[it][2] = CTL[ab + 4];   al[it][3] = CTL[ab + 164];
            }
#pragma unroll
            for (int nt = 0; nt < 4; ++nt) {
                int col = w * 32 + nt * 8 + g;
                int bb = col * 20 + k0w + tig;
                uint32_t bh0 = XTH[bb], bh1 = XTH[bb + 4];
                uint32_t bl0 = XTL[bb], bl1 = XTL[bb + 4];
#pragma unroll
                for (int it = 0; it < 2; ++it) {
                    mma16816(hh[it][nt][0], hh[it][nt][1], hh[it][nt][2], hh[it][nt][3],
                             ah[it][0], ah[it][1], ah[it][2], ah[it][3], bh0, bh1);
                    mma16816(lo[it][nt][0], lo[it][nt][1], lo[it][nt][2], lo[it][nt][3],
                             al[it][0], al[it][1], al[it][2], al[it][3], bh0, bh1);
                    mma16816(lo[it][nt][0], lo[it][nt][1], lo[it][nt][2], lo[it][nt][3],
                             ah[it][0], ah[it][1], ah[it][2], ah[it][3], bl0, bl1);
                }
            }
        }
    }

    // combine + write fp32 partial slab
#pragma unroll
    for (int it = 0; it < 2; ++it)
#pragma unroll
        for (int nt = 0; nt < 4; ++nt) {
            int i = it * 16 + g;
            int m = w * 32 + nt * 8 + 2 * tig;
            size_t base = (((size_t)seg * B_ + b) * NC_ + i) * M_ + m;
            float2 v0, v1;
            v0.x = hh[it][nt][0] + lo[it][nt][0] * (1.0f / 4096.0f);
            v0.y = hh[it][nt][1] + lo[it][nt][1] * (1.0f / 4096.0f);
            v1.x = hh[it][nt][2] + lo[it][nt][2] * (1.0f / 4096.0f);
            v1.y = hh[it][nt][3] + lo[it][nt][3] * (1.0f / 4096.0f);
            *(float2*)(g_cxp + base)          = v0;
            *(float2*)(g_cxp + base + 8 * M_) = v1;
        }
}

extern "C" void kernel_launch(void* const* d_in, const int* in_sizes, int n_in,
                              void* d_out, int out_size) {
    const float* x = (const float*)d_in[0];
    const float* W = (const float*)d_in[1];
    if (n_in >= 2 && in_sizes[0] < in_sizes[1]) {
        const float* tmp = x; x = W; W = tmp;
    }
    float* out = (float*)d_out;

    cudaFuncSetAttribute(k_logits, cudaFuncAttributeMaxDynamicSharedMemorySize, 70656);

    k_prep<<<dim3(B_, SEG_), 256>>>(x);
    k_prepT<<<dim3(B_, 32), 256>>>(x);
    k_caps<0><<<dim3(NC_, 8), 256>>>(W, out);

    k_logits<<<dim3(B_, SEG_), 256, 70656>>>(x);
    k_cx<<<dim3(B_, SEG_), 256>>>(x);
    k_caps<1><<<dim3(NC_, 8), 256>>>(W, out);

    k_logits<<<dim3(B_, SEG_), 256, 70656>>>(x);
    k_cx<<<dim3(B_, SEG_), 256>>>(x);
    k_caps<2><<<dim3(NC_, 8), 256>>>(W, out);
}

// round 10
// speedup vs baseline: 1.2147x; 1.2147x over previous
#include <cuda_runtime.h>
#include <cuda_fp16.h>
#include <cstdint>

#define B_    64
#define J_    1024
#define M_    256
#define NC_   32
#define DC_   32
#define EPS_  1e-7f
#define SEG_  8

// Scratch
__device__ float  g_xsump[SEG_ * B_ * M_];
__device__ float  g_cxp  [SEG_ * B_ * NC_ * M_];
__device__ __half g_wvh  [B_ * NC_ * M_];
__device__ __half g_wvl  [B_ * NC_ * M_];
__device__ __half g_ch   [B_ * NC_ * J_];    // c hi plane, [b][i][j]
__device__ __half g_cl   [B_ * NC_ * J_];    // c lo plane (x4096)
__device__ __half g_xhT  [B_ * M_ * J_];     // x hi plane, transposed [b][m][j]
__device__ __half g_xlT  [B_ * M_ * J_];

// ---------- helpers ----------
__device__ __forceinline__ void splitf(float f, __half& h, __half& l) {
    h = __float2half_rn(f);
    l = __float2half_rn((f - __half2float(h)) * 4096.0f);
}

__device__ __forceinline__ void mma16816(float& c0, float& c1, float& c2, float& c3,
                                         uint32_t a0, uint32_t a1, uint32_t a2, uint32_t a3,
                                         uint32_t b0, uint32_t b1) {
    asm volatile(
        "mma.sync.aligned.m16n8k16.row.col.f32.f16.f16.f32 "
        "{%0,%1,%2,%3}, {%4,%5,%6,%7}, {%8,%9}, {%0,%1,%2,%3};"
        : "+f"(c0), "+f"(c1), "+f"(c2), "+f"(c3)
        : "r"(a0), "r"(a1), "r"(a2), "r"(a3), "r"(b0), "r"(b1));
}

__device__ __forceinline__ void ldmx4t(uint32_t& r0, uint32_t& r1, uint32_t& r2, uint32_t& r3,
                                       uint32_t addr) {
    asm volatile(
        "ldmatrix.sync.aligned.m8n8.x4.trans.shared.b16 {%0,%1,%2,%3}, [%4];"
        : "=r"(r0), "=r"(r1), "=r"(r2), "=r"(r3) : "r"(addr));
}

// ---------- prep: x -> hi/lo TRANSPOSED planes [b][m][j] + fused xsum ----------
// grid (64 b, 8 seg, 4 mc), block 256. Tile: 128 j x 64 m.
__global__ void __launch_bounds__(256) k_prepT(const float* __restrict__ x) {
    __shared__ float S[128 * 65];
    int b = blockIdx.x, seg = blockIdx.y, mc = blockIdx.z;
    int t = threadIdx.x;

#pragma unroll
    for (int c = 0; c < 8; ++c) {
        int lin = t + 256 * c;               // 2048 float4 = 128 j x 16 mq
        int j = lin >> 4, mq = lin & 15;
        float4 v = *(const float4*)(x + ((size_t)b * J_ + seg * 128 + j) * M_ + mc * 64 + mq * 4);
        float* p = S + j * 65 + mq * 4;
        p[0] = v.x; p[1] = v.y; p[2] = v.z; p[3] = v.w;
    }
    __syncthreads();

    int jq = t & 15, mr = t >> 4;
#pragma unroll
    for (int c = 0; c < 4; ++c) {
        int m = mr + 16 * c;
        float f[8]; float s = 0.f;
#pragma unroll
        for (int jj = 0; jj < 8; ++jj) { f[jj] = S[(jq * 8 + jj) * 65 + m]; s += f[jj]; }
        // xsum over the 16 jq-lanes (each holds 8 j)
#pragma unroll
        for (int off = 8; off; off >>= 1) s += __shfl_down_sync(0xffffffffu, s, off, 16);
        if (jq == 0) g_xsump[((size_t)seg * B_ + b) * M_ + mc * 64 + m] = s;

        __half h[8], l[8];
#pragma unroll
        for (int jj = 0; jj < 8; ++jj) splitf(f[jj], h[jj], l[jj]);
        uint4 uh, ul;
        ((__half2*)&uh)[0] = __halves2half2(h[0], h[1]);
        ((__half2*)&uh)[1] = __halves2half2(h[2], h[3]);
        ((__half2*)&uh)[2] = __halves2half2(h[4], h[5]);
        ((__half2*)&uh)[3] = __halves2half2(h[6], h[7]);
        ((__half2*)&ul)[0] = __halves2half2(l[0], l[1]);
        ((__half2*)&ul)[1] = __halves2half2(l[2], l[3]);
        ((__half2*)&ul)[2] = __halves2half2(l[4], l[5]);
        ((__half2*)&ul)[3] = __halves2half2(l[6], l[7]);
        size_t off_ = ((size_t)b * M_ + mc * 64 + m) * J_ + seg * 128 + jq * 8;
        *(uint4*)(g_xhT + off_) = uh;
        *(uint4*)(g_xlT + off_) = ul;
    }
}

// ---------- caps: out = squash(row @ W_i); Wv = W_i @ out (as hi/lo halves) ----------
template <int MODE>
__global__ void __launch_bounds__(256) k_caps(const float* __restrict__ W, float* __restrict__ out) {
    __shared__ float Wsh[M_ * 33];
    __shared__ float rowsh[M_];
    __shared__ float psh[8 * 32];
    __shared__ float osh[NC_];
    int t = threadIdx.x;
    int i = blockIdx.x, bg = blockIdx.y;

#pragma unroll
    for (int c = 0; c < 32; ++c) {
        int lin = t + 256 * c;
        int m = lin >> 5, k = lin & 31;
        Wsh[m * 33 + k] = W[m * (NC_ * DC_) + i * DC_ + k];
    }

    for (int bb = 0; bb < 8; ++bb) {
        int b = bg * 8 + bb;
        float r = 0.f;
        if (MODE == 0) {
#pragma unroll
            for (int s = 0; s < SEG_; ++s) r += g_xsump[((size_t)s * B_ + b) * M_ + t];
        } else {
#pragma unroll
            for (int s = 0; s < SEG_; ++s)
                r += g_cxp[(((size_t)s * B_ + b) * NC_ + i) * M_ + t];
        }
        __syncthreads();
        rowsh[t] = r;
        __syncthreads();

        {
            int k = t & 31, g = t >> 5;
            float p = 0.f;
#pragma unroll
            for (int mm = 0; mm < 32; ++mm)
                p += rowsh[g * 32 + mm] * Wsh[(g * 32 + mm) * 33 + k];
            psh[g * 32 + k] = p;
        }
        __syncthreads();

        if (t < 32) {
            float s = 0.f;
#pragma unroll
            for (int g = 0; g < 8; ++g) s += psh[g * 32 + t];
            float v = (MODE == 0) ? s * (1.0f / 32.0f) : s;
            float sq = v * v;
#pragma unroll
            for (int off = 16; off; off >>= 1) sq += __shfl_xor_sync(0xffffffffu, sq, off);
            float o = v / sqrtf(sq + EPS_);
            osh[t] = o;
            if (MODE == 2) out[((size_t)b * NC_ + i) * DC_ + t] = o;
        }
        __syncthreads();

        if (MODE != 2) {
            float wv = 0.f;
#pragma unroll
            for (int k = 0; k < 32; ++k) wv += Wsh[t * 33 + k] * osh[k];
            __half h, l;
            splitf(wv, h, l);
            g_wvh[((size_t)b * NC_ + i) * M_ + t] = h;
            g_wvl[((size_t)b * NC_ + i) * M_ + t] = l;
        }
        __syncthreads();
    }
}

// ---------- logits + softmax (tensor core, ldmatrix.trans from xT planes) ----------
// grid (64 b, 16 jb), block 256 = 8 warps. Block tile 64 j x 32 i, K = 256 m.
// Warp w: j-tile jt = w&3 (16 j), i-half ih = w>>2 (16 i = 2 n-tiles).
__global__ void __launch_bounds__(256, 3) k_logits() {
    __shared__ __align__(16) __half XH[64 * 72];   // [m][j] per-chunk, pitch 72
    __shared__ __align__(16) __half XL[64 * 72];
    __shared__ __align__(16) __half WHs[32 * 72];  // [i][m] per-chunk
    __shared__ __align__(16) __half WLs[32 * 72];
    __shared__ float b1s[64 * 33];

    int t = threadIdx.x, lane = t & 31, w = t >> 5;
    int jt = w & 3, ih = w >> 2, g = lane >> 2, tig = lane & 3;
    int b = blockIdx.x, jb = blockIdx.y * 64;

    int moff = ((lane >> 4) << 3) + (lane & 7);
    int joff = jt * 16 + (((lane >> 3) & 1) << 3);
    uint32_t aH = (uint32_t)__cvta_generic_to_shared(XH) + 2u * (moff * 72 + joff);
    uint32_t aL = (uint32_t)__cvta_generic_to_shared(XL) + 2u * (moff * 72 + joff);

    float hh[2][4] = {}, lo[2][4] = {};

    for (int kc = 0; kc < 4; ++kc) {       // m-chunks of 64
        __syncthreads();
#pragma unroll
        for (int c = 0; c < 2; ++c) {
            int lin = t + 256 * c;         // 512 uint4 per plane
            int m = lin >> 3, jq = lin & 7;
            size_t so = ((size_t)b * M_ + kc * 64 + m) * J_ + jb + jq * 8;
            *(uint4*)(XH + m * 72 + jq * 8) = *(const uint4*)(g_xhT + so);
            *(uint4*)(XL + m * 72 + jq * 8) = *(const uint4*)(g_xlT + so);
        }
        {
            int i = t >> 3, mq = t & 7;    // 256 uint4 per plane
            size_t so = ((size_t)b * NC_ + i) * M_ + kc * 64 + mq * 8;
            *(uint4*)(WHs + i * 72 + mq * 8) = *(const uint4*)(g_wvh + so);
            *(uint4*)(WLs + i * 72 + mq * 8) = *(const uint4*)(g_wvl + so);
        }
        __syncthreads();

        const uint32_t* WHw = (const uint32_t*)WHs;
        const uint32_t* WLw = (const uint32_t*)WLs;
#pragma unroll
        for (int ks = 0; ks < 4; ++ks) {   // k16 steps
            uint32_t ah0, ah1, ah2, ah3, al0, al1, al2, al3;
            ldmx4t(ah0, ah1, ah2, ah3, aH + ks * 2304);  // 16*72*2 bytes per step
            ldmx4t(al0, al1, al2, al3, aL + ks * 2304);
#pragma unroll
            for (int nt = 0; nt < 2; ++nt) {
                int wi = (ih * 16 + nt * 8 + g) * 36 + ks * 8 + tig;
                uint32_t bh0 = WHw[wi], bh1 = WHw[wi + 4];
                uint32_t bl0 = WLw[wi], bl1 = WLw[wi + 4];
                mma16816(hh[nt][0], hh[nt][1], hh[nt][2], hh[nt][3],
                         ah0, ah1, ah2, ah3, bh0, bh1);
                mma16816(lo[nt][0], lo[nt][1], lo[nt][2], lo[nt][3],
                         al0, al1, al2, al3, bh0, bh1);
                mma16816(lo[nt][0], lo[nt][1], lo[nt][2], lo[nt][3],
                         ah0, ah1, ah2, ah3, bl0, bl1);
            }
        }
    }
    __syncthreads();

#pragma unroll
    for (int nt = 0; nt < 2; ++nt) {
        int r0 = jt * 16 + g, col = ih * 16 + nt * 8 + 2 * tig;
        b1s[r0 * 33 + col]           = hh[nt][0] + lo[nt][0] * (1.0f / 4096.0f);
        b1s[r0 * 33 + col + 1]       = hh[nt][1] + lo[nt][1] * (1.0f / 4096.0f);
        b1s[(r0 + 8) * 33 + col]     = hh[nt][2] + lo[nt][2] * (1.0f / 4096.0f);
        b1s[(r0 + 8) * 33 + col + 1] = hh[nt][3] + lo[nt][3] * (1.0f / 4096.0f);
    }
    __syncthreads();

    // softmax over i per j; stage c hi/lo into WHs/WLs [i][j] (pitch 72)
    if (t < 64) {
        float* row = b1s + t * 33;
        float mx = row[0];
#pragma unroll
        for (int i = 1; i < 32; ++i) mx = fmaxf(mx, row[i]);
        float s = 0.f;
        float e[32];
#pragma unroll
        for (int i = 0; i < 32; ++i) { e[i] = __expf(row[i] - mx); s += e[i]; }
        float inv = 1.0f / s;
#pragma unroll
        for (int i = 0; i < 32; ++i) {
            __half h, l;
            splitf(e[i] * inv, h, l);
            WHs[i * 72 + t] = h;
            WLs[i * 72 + t] = l;
        }
    }
    __syncthreads();
    {
        int i = t >> 3, jq = t & 7;        // 256 uint4 per plane
        size_t off = ((size_t)b * NC_ + i) * J_ + jb + jq * 8;
        *(uint4*)(g_ch + off) = *(const uint4*)(WHs + i * 72 + jq * 8);
        *(uint4*)(g_cl + off) = *(const uint4*)(WLs + i * 72 + jq * 8);
    }
}

// ---------- cx partials (tensor core) ----------
// grid (64 b, 8 seg, 2 mhalf), block 256 = 8 warps.
// Warp w: m-group mg = w>>1 (32 m = 4 n-tiles), i-tile it = w&1. K = 128 j in 4 chunks.
__global__ void __launch_bounds__(256, 3) k_cx() {
    __shared__ __align__(16) __half XTs0[128 * 40];  // x hi [m][j], pitch 40
    __shared__ __align__(16) __half XTs1[128 * 40];
    __shared__ __align__(16) __half CTs0[32 * 40];   // c hi [i][j]
    __shared__ __align__(16) __half CTs1[32 * 40];

    int t = threadIdx.x, lane = t & 31, w = t >> 5;
    int mg = w >> 1, it = w & 1, g = lane >> 2, tig = lane & 3;
    int b = blockIdx.x, seg = blockIdx.y, z = blockIdx.z;

    float hh[4][4] = {}, lo[4][4] = {};

    for (int jc = 0; jc < 4; ++jc) {
        __syncthreads();
        int jb = seg * 128 + jc * 32;
#pragma unroll
        for (int c = 0; c < 2; ++c) {
            int lin = t + 256 * c;         // 512 uint4 per plane
            int m = lin >> 2, jq = lin & 3;
            size_t so = ((size_t)b * M_ + z * 128 + m) * J_ + jb + jq * 8;
            *(uint4*)(XTs0 + m * 40 + jq * 8) = *(const uint4*)(g_xhT + so);
            *(uint4*)(XTs1 + m * 40 + jq * 8) = *(const uint4*)(g_xlT + so);
        }
        if (t < 128) {
            int i = t >> 2, jq = t & 3;    // 128 uint4 per plane
            size_t so = ((size_t)b * NC_ + i) * J_ + jb + jq * 8;
            *(uint4*)(CTs0 + i * 40 + jq * 8) = *(const uint4*)(g_ch + so);
            *(uint4*)(CTs1 + i * 40 + jq * 8) = *(const uint4*)(g_cl + so);
        }
        __syncthreads();

        const uint32_t* XTH = (const uint32_t*)XTs0;
        const uint32_t* XTL = (const uint32_t*)XTs1;
        const uint32_t* CTH = (const uint32_t*)CTs0;
        const uint32_t* CTL = (const uint32_t*)CTs1;
#pragma unroll
        for (int ks = 0; ks < 2; ++ks) {
            int ab = (it * 16 + g) * 20 + ks * 8 + tig;
            uint32_t ah0 = CTH[ab], ah1 = CTH[ab + 160], ah2 = CTH[ab + 4], ah3 = CTH[ab + 164];
            uint32_t al0 = CTL[ab], al1 = CTL[ab + 160], al2 = CTL[ab + 4], al3 = CTL[ab + 164];
#pragma unroll
            for (int nt = 0; nt < 4; ++nt) {
                int bb = (mg * 32 + nt * 8 + g) * 20 + ks * 8 + tig;
                uint32_t bh0 = XTH[bb], bh1 = XTH[bb + 4];
                uint32_t bl0 = XTL[bb], bl1 = XTL[bb + 4];
                mma16816(hh[nt][0], hh[nt][1], hh[nt][2], hh[nt][3],
                         ah0, ah1, ah2, ah3, bh0, bh1);
                mma16816(lo[nt][0], lo[nt][1], lo[nt][2], lo[nt][3],
                         al0, al1, al2, al3, bh0, bh1);
                mma16816(lo[nt][0], lo[nt][1], lo[nt][2], lo[nt][3],
                         ah0, ah1, ah2, ah3, bl0, bl1);
            }
        }
    }

#pragma unroll
    for (int nt = 0; nt < 4; ++nt) {
        int i = it * 16 + g;
        int m = z * 128 + mg * 32 + nt * 8 + 2 * tig;
        size_t base = (((size_t)seg * B_ + b) * NC_ + i) * M_ + m;
        float2 v0, v1;
        v0.x = hh[nt][0] + lo[nt][0] * (1.0f / 4096.0f);
        v0.y = hh[nt][1] + lo[nt][1] * (1.0f / 4096.0f);
        v1.x = hh[nt][2] + lo[nt][2] * (1.0f / 4096.0f);
        v1.y = hh[nt][3] + lo[nt][3] * (1.0f / 4096.0f);
        *(float2*)(g_cxp + base)          = v0;
        *(float2*)(g_cxp + base + 8 * M_) = v1;
    }
}

extern "C" void kernel_launch(void* const* d_in, const int* in_sizes, int n_in,
                              void* d_out, int out_size) {
    const float* x = (const float*)d_in[0];
    const float* W = (const float*)d_in[1];
    if (n_in >= 2 && in_sizes[0] < in_sizes[1]) {
        const float* tmp = x; x = W; W = tmp;
    }
    float* out = (float*)d_out;

    k_prepT<<<dim3(B_, SEG_, 4), 256>>>(x);
    k_caps<0><<<dim3(NC_, 8), 256>>>(W, out);

    k_logits<<<dim3(B_, 16), 256>>>();
    k_cx<<<dim3(B_, SEG_, 2), 256>>>();
    k_caps<1><<<dim3(NC_, 8), 256>>>(W, out);

    k_logits<<<dim3(B_, 16), 256>>>();
    k_cx<<<dim3(B_, SEG_, 2), 256>>>();
    k_caps<2><<<dim3(NC_, 8), 256>>>(W, out);
}